// round 4
// baseline (speedup 1.0000x reference)
#include <cuda_runtime.h>
#include <math.h>
#include <stdint.h>

#define BATCH 8
#define NINST 8192
#define DIM   512
#define HID   64
#define TOPK_K 2457

// gather chunking
#define GCHUNKS 64
#define GROWS   (NINST / GCHUNKS)   // 128

// mlp split-K
#define KCHUNKS 8
#define KLEN    (DIM / KCHUNKS)     // 64

// attn GEMM K-chunk
#define KC 16

// scratch (device globals; no allocation allowed)
__device__ float    g_w1hi[DIM * HID];               // aW1 tf32 high part
__device__ float    g_w1lo[DIM * HID];               // aW1 tf32 low  part
__device__ float    g_part[GCHUNKS * BATCH * DIM];   // gather partials
__device__ float    g_emb[BATCH * DIM];              // pooled embedding
__device__ float    g_p1[KCHUNKS * BATCH * DIM];     // mlp1 partials
__device__ float    g_h1[BATCH * DIM];               // mlp1 output
__device__ float    g_p2[KCHUNKS * BATCH * DIM];     // mlp2 partials
__device__ unsigned g_thr[BATCH];                    // k-th largest weight (bits)
__device__ int      g_cut[BATCH];                    // tie cutoff index

__device__ __forceinline__ float gelu_f(float v) {
    float u = 0.7978845608028654f * (v + 0.044715f * v * v * v);
    return 0.5f * v * (1.0f + tanhf(u));
}

__device__ __forceinline__ uint32_t tf32_of(float v) {
    uint32_t u;
    asm("cvt.rna.tf32.f32 %0, %1;" : "=r"(u) : "f"(v));
    return u;
}

__device__ __forceinline__ void mma_tf32(float* c, const uint32_t* a, const uint32_t* b) {
    asm volatile(
        "mma.sync.aligned.m16n8k8.row.col.f32.tf32.tf32.f32 "
        "{%0,%1,%2,%3}, {%4,%5,%6,%7}, {%8,%9}, {%0,%1,%2,%3};"
        : "+f"(c[0]), "+f"(c[1]), "+f"(c[2]), "+f"(c[3])
        : "r"(a[0]), "r"(a[1]), "r"(a[2]), "r"(a[3]), "r"(b[0]), "r"(b[1]));
}

__device__ __forceinline__ void cp16(uint32_t sdst, const void* gsrc) {
    asm volatile("cp.async.cg.shared.global [%0], [%1], 16;" :: "r"(sdst), "l"(gsrc));
}

// ---------------------------------------------------------------------------
// Kernel 0: split aW1 into tf32 hi/lo parts (3xTF32 scheme).
// ---------------------------------------------------------------------------
__global__ __launch_bounds__(256) void conv_w1_kernel(const float* __restrict__ aW1)
{
    int i = blockIdx.x * 256 + threadIdx.x;
    if (i < DIM * HID) {
        float v  = aW1[i];
        float hi = __uint_as_float(tf32_of(v));
        float lo = __uint_as_float(tf32_of(v - hi));
        g_w1hi[i] = hi;
        g_w1lo[i] = lo;
    }
}

// ---------------------------------------------------------------------------
// Kernel 1: fused attention-score MLP, 3xTF32 tensor-core GEMM.
// Block tile 128 rows x 64 hid, 256 threads = 8 warps (4M x 2N),
// warp tile 32x32, K chunked by 16, 2-stage cp.async double buffer.
// acc += Ahi*Bhi + Ahi*Blo + Alo*Bhi   (fp32 accumulate)
// ---------------------------------------------------------------------------
__global__ __launch_bounds__(256) void attn_kernel(
    const float* __restrict__ x,
    const float* __restrict__ ab1,
    const float* __restrict__ aW2,
    const float* __restrict__ ab2,
    float* __restrict__ wout)
{
    __shared__ __align__(16) float As[2][128][20];  // [stage][row][k] pad 20
    __shared__ __align__(16) float Bh[2][KC][72];   // [stage][k][n] hi, pad 72
    __shared__ __align__(16) float Bl[2][KC][72];   // [stage][k][n] lo
    __shared__ float red[128][2];

    const int tid   = threadIdx.x;
    const int lane  = tid & 31;
    const int warp  = tid >> 5;
    const int warpM = warp >> 1;     // 0..3
    const int warpN = warp & 1;      // 0..1
    const long rowBase = (long)blockIdx.x * 128;
    const float* xb = x + rowBase * DIM;

    float acc[2][4][4];
    #pragma unroll
    for (int mi = 0; mi < 2; mi++)
        #pragma unroll
        for (int ni = 0; ni < 4; ni++)
            #pragma unroll
            for (int q = 0; q < 4; q++) acc[mi][ni][q] = 0.f;

    auto load_tiles = [&](int stage, int kk) {
        // A: 128 rows x 16 floats = 512 float4, 2 per thread
        #pragma unroll
        for (int q = 0; q < 2; q++) {
            int idx = q * 256 + tid;
            int r = idx >> 2, c = idx & 3;
            uint32_t dst = (uint32_t)__cvta_generic_to_shared(&As[stage][r][c * 4]);
            cp16(dst, xb + (long)r * DIM + kk + c * 4);
        }
        // B hi / lo: 16 x 64 = 256 float4 each, 1 per thread
        {
            int r = tid >> 4, c = tid & 15;
            uint32_t dh = (uint32_t)__cvta_generic_to_shared(&Bh[stage][r][c * 4]);
            cp16(dh, g_w1hi + (kk + r) * HID + c * 4);
            uint32_t dl = (uint32_t)__cvta_generic_to_shared(&Bl[stage][r][c * 4]);
            cp16(dl, g_w1lo + (kk + r) * HID + c * 4);
        }
        asm volatile("cp.async.commit_group;");
    };

    load_tiles(0, 0);

    const int lk = lane & 3;       // k sub-index
    const int lr = lane >> 2;      // row/col sub-index

    for (int ch = 0; ch < DIM / KC; ch++) {
        if (ch < DIM / KC - 1) {
            load_tiles((ch + 1) & 1, (ch + 1) * KC);
            asm volatile("cp.async.wait_group 1;");
        } else {
            asm volatile("cp.async.wait_group 0;");
        }
        __syncthreads();
        const int st = ch & 1;

        #pragma unroll
        for (int ks = 0; ks < KC / 8; ks++) {
            const int k0 = ks * 8;
            uint32_t ahi[2][4], alo[2][4];
            #pragma unroll
            for (int mi = 0; mi < 2; mi++) {
                int rr = warpM * 32 + mi * 16 + lr;
                float v0 = As[st][rr][k0 + lk];
                float v1 = As[st][rr + 8][k0 + lk];
                float v2 = As[st][rr][k0 + lk + 4];
                float v3 = As[st][rr + 8][k0 + lk + 4];
                ahi[mi][0] = tf32_of(v0);
                ahi[mi][1] = tf32_of(v1);
                ahi[mi][2] = tf32_of(v2);
                ahi[mi][3] = tf32_of(v3);
                alo[mi][0] = tf32_of(v0 - __uint_as_float(ahi[mi][0]));
                alo[mi][1] = tf32_of(v1 - __uint_as_float(ahi[mi][1]));
                alo[mi][2] = tf32_of(v2 - __uint_as_float(ahi[mi][2]));
                alo[mi][3] = tf32_of(v3 - __uint_as_float(ahi[mi][3]));
            }
            uint32_t bhi[4][2], blo[4][2];
            #pragma unroll
            for (int ni = 0; ni < 4; ni++) {
                int cc = warpN * 32 + ni * 8 + lr;
                bhi[ni][0] = __float_as_uint(Bh[st][k0 + lk][cc]);
                bhi[ni][1] = __float_as_uint(Bh[st][k0 + lk + 4][cc]);
                blo[ni][0] = __float_as_uint(Bl[st][k0 + lk][cc]);
                blo[ni][1] = __float_as_uint(Bl[st][k0 + lk + 4][cc]);
            }
            #pragma unroll
            for (int mi = 0; mi < 2; mi++)
                #pragma unroll
                for (int ni = 0; ni < 4; ni++) {
                    mma_tf32(acc[mi][ni], ahi[mi], bhi[ni]);
                    mma_tf32(acc[mi][ni], ahi[mi], blo[ni]);
                    mma_tf32(acc[mi][ni], alo[mi], bhi[ni]);
                }
        }
        __syncthreads();
    }

    // epilogue: gelu(acc + b1) . w2, row-reduce, sigmoid
    float b1v[4][2], w2v[4][2];
    #pragma unroll
    for (int ni = 0; ni < 4; ni++) {
        int col = warpN * 32 + ni * 8 + 2 * lk;
        b1v[ni][0] = ab1[col];     b1v[ni][1] = ab1[col + 1];
        w2v[ni][0] = aW2[col];     w2v[ni][1] = aW2[col + 1];
    }

    float p[2][2] = {{0.f, 0.f}, {0.f, 0.f}};
    #pragma unroll
    for (int mi = 0; mi < 2; mi++)
        #pragma unroll
        for (int ni = 0; ni < 4; ni++) {
            p[mi][0] += gelu_f(acc[mi][ni][0] + b1v[ni][0]) * w2v[ni][0]
                      + gelu_f(acc[mi][ni][1] + b1v[ni][1]) * w2v[ni][1];
            p[mi][1] += gelu_f(acc[mi][ni][2] + b1v[ni][0]) * w2v[ni][0]
                      + gelu_f(acc[mi][ni][3] + b1v[ni][1]) * w2v[ni][1];
        }
    #pragma unroll
    for (int mi = 0; mi < 2; mi++) {
        #pragma unroll
        for (int h = 0; h < 2; h++) {
            p[mi][h] += __shfl_xor_sync(0xffffffffu, p[mi][h], 1);
            p[mi][h] += __shfl_xor_sync(0xffffffffu, p[mi][h], 2);
        }
    }
    if (lk == 0) {
        #pragma unroll
        for (int mi = 0; mi < 2; mi++) {
            int r = warpM * 32 + mi * 16 + lr;
            red[r][warpN]     = p[mi][0];
            red[r + 8][warpN] = p[mi][1];
        }
    }
    __syncthreads();
    if (tid < 128) {
        float s = red[tid][0] + red[tid][1] + ab2[0];
        wout[rowBase + tid] = 1.0f / (1.0f + expf(-s));
    }
}

// ---------------------------------------------------------------------------
// Kernel 2: per-batch radix-select (4x8-bit) + exact tie cutoff by lowest idx.
// ---------------------------------------------------------------------------
__global__ __launch_bounds__(256) void select_kernel(const float* __restrict__ w)
{
    __shared__ unsigned sv[NINST];
    __shared__ int hist[8][256];
    __shared__ int tcnt[256];
    __shared__ unsigned s_prefix;
    __shared__ int s_k;

    const int b = blockIdx.x;
    const int tid = threadIdx.x;
    const int wid = tid >> 5;
    const float* wb = w + b * NINST;

    for (int i = tid; i < NINST; i += 256)
        sv[i] = __float_as_uint(wb[i]);   // weights > 0 -> uint order == float order
    if (tid == 0) { s_prefix = 0u; s_k = TOPK_K; }
    __syncthreads();

    for (int r = 0; r < 4; r++) {
        #pragma unroll
        for (int h = 0; h < 8; h++) hist[h][tid] = 0;
        __syncthreads();
        const unsigned pref = s_prefix;
        const int sh = 24 - 8 * r;
        for (int i = tid; i < NINST; i += 256) {
            unsigned v = sv[i];
            bool ok = (r == 0) || ((v >> (sh + 8)) == pref);
            if (ok) atomicAdd(&hist[wid][(v >> sh) & 255], 1);
        }
        __syncthreads();
        int s = hist[0][tid];
        #pragma unroll
        for (int h = 1; h < 8; h++) s += hist[h][tid];
        hist[0][tid] = s;
        __syncthreads();
        if (tid == 0) {
            int k = s_k, cum = 0, bsel = 0;
            for (int bb = 255; bb >= 0; --bb) {
                cum += hist[0][bb];
                if (cum >= k) { bsel = bb; s_k = k - (cum - hist[0][bb]); break; }
            }
            s_prefix = (pref << 8) | (unsigned)bsel;
        }
        __syncthreads();
    }

    const unsigned thrv = s_prefix;
    const int m = s_k;               // #ties to include (>= 1)

    const int base = tid * (NINST / 256);
    int local = 0;
    #pragma unroll 4
    for (int i = 0; i < NINST / 256; i++)
        if (sv[base + i] == thrv) local++;
    tcnt[tid] = local;
    __syncthreads();
    if (tid == 0) {
        int s = 0;
        for (int t = 0; t < 256; t++) { int c = tcnt[t]; tcnt[t] = s; s += c; }
    }
    __syncthreads();
    int rank = tcnt[tid];
    for (int i = 0; i < NINST / 256; i++) {
        if (sv[base + i] == thrv) {
            rank++;
            if (rank == m) g_cut[b] = base + i;
        }
    }
    if (tid == 0) g_thr[b] = thrv;
}

// ---------------------------------------------------------------------------
// Kernel 3: weighted gather-sum. One block per (batch, 128-row chunk).
// ---------------------------------------------------------------------------
__global__ __launch_bounds__(128) void gather_kernel(
    const float* __restrict__ x, const float* __restrict__ w)
{
    const int b  = blockIdx.y;
    const int rc = blockIdx.x;
    const int r0 = rc * GROWS;
    const int d4 = threadIdx.x * 4;

    const unsigned tv = g_thr[b];
    const int cu = g_cut[b];
    const float* wb = w + b * NINST + r0;
    const float* xb = x + ((long)b * NINST + r0) * DIM + d4;

    float4 acc = make_float4(0.f, 0.f, 0.f, 0.f);
    float wnext = wb[0];
    #pragma unroll 4
    for (int i = 0; i < GROWS; i++) {
        float wi = wnext;
        if (i + 1 < GROWS) wnext = wb[i + 1];
        unsigned v = __float_as_uint(wi);
        if (v > tv || (v == tv && (r0 + i) <= cu)) {
            float4 xv = *reinterpret_cast<const float4*>(xb + (long)i * DIM);
            acc.x += wi * xv.x; acc.y += wi * xv.y;
            acc.z += wi * xv.z; acc.w += wi * xv.w;
        }
    }
    *reinterpret_cast<float4*>(&g_part[(rc * BATCH + b) * DIM + d4]) = acc;
}

// ---------------------------------------------------------------------------
// Kernel 4: emb[b,d] = (sum of partials) / TOPK.  grid=BATCH, block=512.
// ---------------------------------------------------------------------------
__global__ __launch_bounds__(512) void emb_kernel()
{
    const int b = blockIdx.x;
    const int d = threadIdx.x;
    float s = 0.f;
    #pragma unroll
    for (int rc = 0; rc < GCHUNKS; rc++)
        s += g_part[(rc * BATCH + b) * DIM + d];
    g_emb[b * DIM + d] = s * (1.0f / (float)TOPK_K);
}

// ---------------------------------------------------------------------------
// Kernels 5/7: split-K GEMM partials for the projection MLP.
// ---------------------------------------------------------------------------
__global__ __launch_bounds__(128) void mlp_part_kernel(
    const float* __restrict__ in,   // [B, DIM]
    const float* __restrict__ W,    // [DIM, DIM]
    float* __restrict__ part)       // [KCHUNKS, B, DIM]
{
    __shared__ float s_in[BATCH][KLEN];
    const int kc = blockIdx.y;
    const int j  = blockIdx.x * 128 + threadIdx.x;

    #pragma unroll
    for (int it = 0; it < (BATCH * KLEN) / 128; it++) {
        int i = it * 128 + threadIdx.x;
        int bb = i / KLEN, dd = i % KLEN;
        s_in[bb][dd] = in[bb * DIM + kc * KLEN + dd];
    }
    __syncthreads();

    float acc[BATCH];
    #pragma unroll
    for (int bb = 0; bb < BATCH; bb++) acc[bb] = 0.f;

    #pragma unroll 4
    for (int dd = 0; dd < KLEN; dd++) {
        float wv = W[(long)(kc * KLEN + dd) * DIM + j];
        #pragma unroll
        for (int bb = 0; bb < BATCH; bb++)
            acc[bb] += s_in[bb][dd] * wv;
    }
    #pragma unroll
    for (int bb = 0; bb < BATCH; bb++)
        part[(kc * BATCH + bb) * DIM + j] = acc[bb];
}

__global__ __launch_bounds__(512) void mlp1_reduce_kernel(const float* __restrict__ bias)
{
    const int b = blockIdx.x;
    const int j = threadIdx.x;
    float s = 0.f;
    #pragma unroll
    for (int kc = 0; kc < KCHUNKS; kc++)
        s += g_p1[(kc * BATCH + b) * DIM + j];
    g_h1[b * DIM + j] = gelu_f(s + bias[j]);
}

__global__ __launch_bounds__(512) void mlp2_reduce_kernel(
    const float* __restrict__ bias, float* __restrict__ out)
{
    const int b = blockIdx.x;
    const int j = threadIdx.x;
    float s = 0.f;
    #pragma unroll
    for (int kc = 0; kc < KCHUNKS; kc++)
        s += g_p2[(kc * BATCH + b) * DIM + j];
    out[b * DIM + j] = s + bias[j];
}

// ---------------------------------------------------------------------------
extern "C" void kernel_launch(void* const* d_in, const int* in_sizes, int n_in,
                              void* d_out, int out_size)
{
    const float* x   = (const float*)d_in[0];
    const float* aW1 = (const float*)d_in[1];
    const float* ab1 = (const float*)d_in[2];
    const float* aW2 = (const float*)d_in[3];
    const float* ab2 = (const float*)d_in[4];
    const float* pW1 = (const float*)d_in[5];
    const float* pb1 = (const float*)d_in[6];
    const float* pW2 = (const float*)d_in[7];
    const float* pb2 = (const float*)d_in[8];

    float* out = (float*)d_out;
    float* proj    = out;                 // [B, DIM]
    float* weights = out + BATCH * DIM;   // [B, NINST]

    float* d_p1;  cudaGetSymbolAddress((void**)&d_p1, g_p1);
    float* d_p2;  cudaGetSymbolAddress((void**)&d_p2, g_p2);
    float* d_emb; cudaGetSymbolAddress((void**)&d_emb, g_emb);
    float* d_h1;  cudaGetSymbolAddress((void**)&d_h1, g_h1);

    conv_w1_kernel<<<(DIM * HID + 255) / 256, 256>>>(aW1);
    attn_kernel<<<(BATCH * NINST) / 128, 256>>>(x, ab1, aW2, ab2, weights);
    select_kernel<<<BATCH, 256>>>(weights);
    gather_kernel<<<dim3(GCHUNKS, BATCH), 128>>>(x, weights);
    emb_kernel<<<BATCH, 512>>>();
    mlp_part_kernel<<<dim3(DIM / 128, KCHUNKS), 128>>>(d_emb, pW1, d_p1);
    mlp1_reduce_kernel<<<BATCH, 512>>>(pb1);
    mlp_part_kernel<<<dim3(DIM / 128, KCHUNKS), 128>>>(d_h1, pW2, d_p2);
    mlp2_reduce_kernel<<<BATCH, 512>>>(pb2, proj);
}

// round 6
// speedup vs baseline: 1.4577x; 1.4577x over previous
#include <cuda_runtime.h>
#include <cuda_bf16.h>
#include <math.h>
#include <stdint.h>

#define BATCH 8
#define NINST 8192
#define DIM   512
#define HID   64
#define TOPK_K 2457

#define GCHUNKS 64
#define GROWS   (NINST / GCHUNKS)   // 128

#define KCHUNKS 16
#define KLEN    (DIM / KCHUNKS)     // 32

// attn tiling
#define BM 128
#define BN 64
#define BK 32
#define NCH (DIM / BK)              // 16

#define CAP  512
#define BAND 1e-4f

// scratch (device globals; no allocation allowed)
__device__ __align__(16) __nv_bfloat16 g_w1bh[DIM * HID];  // aW1 hi, [k][n]
__device__ __align__(16) __nv_bfloat16 g_w1bl[DIM * HID];  // aW1 lo, [k][n]
__device__ float    g_part[GCHUNKS * BATCH * DIM];
__device__ float    g_emb[BATCH * DIM];
__device__ float    g_p1[KCHUNKS * BATCH * DIM];
__device__ float    g_h1[BATCH * DIM];
__device__ float    g_p2[KCHUNKS * BATCH * DIM];
__device__ unsigned g_thr[BATCH];                 // approx kth weight (bits)
__device__ int      g_above[BATCH];               // #(w > thr+BAND)
__device__ int      g_ccnt[BATCH];                // candidate count
__device__ int      g_cand[BATCH][CAP];           // candidate indices
__device__ float    g_cval[BATCH][CAP];           // refined fp32 weights
__device__ unsigned char g_flag[BATCH * NINST];   // boundary-selected flags

__device__ __forceinline__ float gelu_f(float v) {
    float u = 0.7978845608028654f * (v + 0.044715f * v * v * v);
    return 0.5f * v * (1.0f + tanhf(u));
}

__device__ __forceinline__ void cp16(uint32_t sdst, const void* gsrc) {
    asm volatile("cp.async.cg.shared.global [%0], [%1], 16;" :: "r"(sdst), "l"(gsrc));
}

__device__ __forceinline__ void hmma(float* c, const unsigned* a, const unsigned* b) {
    asm volatile(
        "mma.sync.aligned.m16n8k16.row.col.f32.bf16.bf16.f32 "
        "{%0,%1,%2,%3}, {%4,%5,%6,%7}, {%8,%9}, {%0,%1,%2,%3};"
        : "+f"(c[0]), "+f"(c[1]), "+f"(c[2]), "+f"(c[3])
        : "r"(a[0]), "r"(a[1]), "r"(a[2]), "r"(a[3]), "r"(b[0]), "r"(b[1]));
}

__device__ __forceinline__ void ldm_x4(unsigned* r, uint32_t addr) {
    asm volatile("ldmatrix.sync.aligned.m8n8.x4.shared.b16 {%0,%1,%2,%3}, [%4];"
                 : "=r"(r[0]), "=r"(r[1]), "=r"(r[2]), "=r"(r[3]) : "r"(addr));
}
__device__ __forceinline__ void ldm_x4t(unsigned* r, uint32_t addr) {
    asm volatile("ldmatrix.sync.aligned.m8n8.x4.trans.shared.b16 {%0,%1,%2,%3}, [%4];"
                 : "=r"(r[0]), "=r"(r[1]), "=r"(r[2]), "=r"(r[3]) : "r"(addr));
}

// ---------------------------------------------------------------------------
// Kernel 0: bf16 hi/lo split of aW1 (layout unchanged, [k][n]).
// ---------------------------------------------------------------------------
__global__ __launch_bounds__(256) void conv_w1_kernel(const float* __restrict__ aW1)
{
    int i = blockIdx.x * 256 + threadIdx.x;
    if (i < DIM * HID) {
        float v = aW1[i];
        __nv_bfloat16 h = __float2bfloat16_rn(v);
        __nv_bfloat16 l = __float2bfloat16_rn(v - __bfloat162float(h));
        g_w1bh[i] = h;
        g_w1bl[i] = l;
    }
}

// ---------------------------------------------------------------------------
// Kernel 1: fused attention-score MLP, bf16 HMMA (3-term hi/lo emulation).
// Block: 128 rows x 64 hid, 256 threads = 8 warps (4M x 2N), warp tile 32x32.
// K chunked by 32; A converted fp32->bf16 hi/lo in-kernel; B cp.async 2-stage.
// ---------------------------------------------------------------------------
__global__ __launch_bounds__(256) void attn_kernel(
    const float* __restrict__ x,
    const float* __restrict__ ab1,
    const float* __restrict__ aW2,
    const float* __restrict__ ab2,
    float* __restrict__ wout)
{
    __shared__ __align__(16) __nv_bfloat16 Ah[BM][40];      // stride 40 (no conflicts)
    __shared__ __align__(16) __nv_bfloat16 Al[BM][40];
    __shared__ __align__(16) __nv_bfloat16 Bh[2][BK][72];   // stride 72 (no conflicts)
    __shared__ __align__(16) __nv_bfloat16 Bl[2][BK][72];
    __shared__ float red[128][2];

    const int tid   = threadIdx.x;
    const int lane  = tid & 31;
    const int warp  = tid >> 5;
    const int warpM = warp >> 1;     // 0..3
    const int warpN = warp & 1;      // 0..1
    const long rowBase = (long)blockIdx.x * BM;
    const float* xb = x + rowBase * DIM;

    float acc[2][4][4];
    #pragma unroll
    for (int mi = 0; mi < 2; mi++)
        #pragma unroll
        for (int ni = 0; ni < 4; ni++)
            #pragma unroll
            for (int q = 0; q < 4; q++) acc[mi][ni][q] = 0.f;

    // B loader: chunk c -> stage s. 32 rows x 64 bf16 = 256 granules of 16B; one
    // hi + one lo granule per thread.
    auto loadB = [&](int s, int c) {
        int r = tid >> 3, g = tid & 7;
        uint32_t dh = (uint32_t)__cvta_generic_to_shared(&Bh[s][r][g * 8]);
        cp16(dh, g_w1bh + (c * BK + r) * HID + g * 8);
        uint32_t dl = (uint32_t)__cvta_generic_to_shared(&Bl[s][r][g * 8]);
        cp16(dl, g_w1bl + (c * BK + r) * HID + g * 8);
        asm volatile("cp.async.commit_group;");
    };

    // A slice: row ar, half ah (16 contiguous floats of the 32-wide chunk)
    const int ar = tid >> 1;
    const int ah = tid & 1;
    const float* xrow = xb + (long)ar * DIM + ah * 16;

    loadB(0, 0);
    float4 xr[4];
    #pragma unroll
    for (int q = 0; q < 4; q++)
        xr[q] = *reinterpret_cast<const float4*>(xrow + q * 4);

    for (int c = 0; c < NCH; c++) {
        // convert 16 floats -> 8 hi words + 8 lo words (bf16x2)
        unsigned hw[8], lw[8];
        const float* xv = reinterpret_cast<const float*>(xr);
        #pragma unroll
        for (int e = 0; e < 8; e++) {
            float v0 = xv[2 * e], v1 = xv[2 * e + 1];
            __nv_bfloat16 h0 = __float2bfloat16_rn(v0);
            __nv_bfloat16 l0 = __float2bfloat16_rn(v0 - __bfloat162float(h0));
            __nv_bfloat16 h1 = __float2bfloat16_rn(v1);
            __nv_bfloat16 l1 = __float2bfloat16_rn(v1 - __bfloat162float(h1));
            __nv_bfloat162 hp = __halves2bfloat162(h0, h1);
            __nv_bfloat162 lp = __halves2bfloat162(l0, l1);
            hw[e] = *reinterpret_cast<unsigned*>(&hp);
            lw[e] = *reinterpret_cast<unsigned*>(&lp);
        }
        // prefetch next chunk
        float4 xn[4];
        if (c + 1 < NCH) {
            #pragma unroll
            for (int q = 0; q < 4; q++)
                xn[q] = *reinterpret_cast<const float4*>(xrow + (c + 1) * BK + q * 4);
        }
        __syncthreads();   // prior iteration's ldmatrix reads complete

        // store A hi/lo (bf16 col = ah*16 + 2e)
        {
            char* pa = reinterpret_cast<char*>(&Ah[0][0]) + ar * 80 + ah * 32;
            char* pl = reinterpret_cast<char*>(&Al[0][0]) + ar * 80 + ah * 32;
            *reinterpret_cast<uint4*>(pa)      = make_uint4(hw[0], hw[1], hw[2], hw[3]);
            *reinterpret_cast<uint4*>(pa + 16) = make_uint4(hw[4], hw[5], hw[6], hw[7]);
            *reinterpret_cast<uint4*>(pl)      = make_uint4(lw[0], lw[1], lw[2], lw[3]);
            *reinterpret_cast<uint4*>(pl + 16) = make_uint4(lw[4], lw[5], lw[6], lw[7]);
        }
        if (c + 1 < NCH) {
            loadB((c + 1) & 1, c + 1);
            asm volatile("cp.async.wait_group 1;");
        } else {
            asm volatile("cp.async.wait_group 0;");
        }
        __syncthreads();   // A stores + B chunk c visible

        const int st = c & 1;
        #pragma unroll
        for (int ks = 0; ks < 2; ks++) {
            const int k0 = ks * 16;
            unsigned Ahf[2][4], Alf[2][4];
            #pragma unroll
            for (int mi = 0; mi < 2; mi++) {
                int arow2 = warpM * 32 + mi * 16 + (lane & 15);
                int acol  = k0 + ((lane >> 4) << 3);
                uint32_t base = (uint32_t)__cvta_generic_to_shared(&Ah[arow2][acol]);
                ldm_x4(Ahf[mi], base);
                uint32_t basel = (uint32_t)__cvta_generic_to_shared(&Al[arow2][acol]);
                ldm_x4(Alf[mi], basel);
            }
            unsigned Bhf[4][2], Blf[4][2];
            #pragma unroll
            for (int pr = 0; pr < 2; pr++) {
                int brow = k0 + (lane & 15);
                int bcol = warpN * 32 + pr * 16 + ((lane >> 4) << 3);
                unsigned t4[4];
                uint32_t bb = (uint32_t)__cvta_generic_to_shared(&Bh[st][brow][bcol]);
                ldm_x4t(t4, bb);
                Bhf[pr * 2][0] = t4[0]; Bhf[pr * 2][1] = t4[1];
                Bhf[pr * 2 + 1][0] = t4[2]; Bhf[pr * 2 + 1][1] = t4[3];
                uint32_t bl = (uint32_t)__cvta_generic_to_shared(&Bl[st][brow][bcol]);
                ldm_x4t(t4, bl);
                Blf[pr * 2][0] = t4[0]; Blf[pr * 2][1] = t4[1];
                Blf[pr * 2 + 1][0] = t4[2]; Blf[pr * 2 + 1][1] = t4[3];
            }
            #pragma unroll
            for (int mi = 0; mi < 2; mi++)
                #pragma unroll
                for (int ni = 0; ni < 4; ni++) {
                    hmma(acc[mi][ni], Ahf[mi], Bhf[ni]);
                    hmma(acc[mi][ni], Ahf[mi], Blf[ni]);
                    hmma(acc[mi][ni], Alf[mi], Bhf[ni]);
                }
        }
        #pragma unroll
        for (int q = 0; q < 4; q++) xr[q] = xn[q];
    }

    // epilogue: gelu(acc + b1) . w2, row-reduce, sigmoid  (layout validated R4)
    const int lk = lane & 3;
    const int lr = lane >> 2;
    float b1v[4][2], w2v[4][2];
    #pragma unroll
    for (int ni = 0; ni < 4; ni++) {
        int col = warpN * 32 + ni * 8 + 2 * lk;
        b1v[ni][0] = ab1[col];     b1v[ni][1] = ab1[col + 1];
        w2v[ni][0] = aW2[col];     w2v[ni][1] = aW2[col + 1];
    }
    float p[2][2] = {{0.f, 0.f}, {0.f, 0.f}};
    #pragma unroll
    for (int mi = 0; mi < 2; mi++)
        #pragma unroll
        for (int ni = 0; ni < 4; ni++) {
            p[mi][0] += gelu_f(acc[mi][ni][0] + b1v[ni][0]) * w2v[ni][0]
                      + gelu_f(acc[mi][ni][1] + b1v[ni][1]) * w2v[ni][1];
            p[mi][1] += gelu_f(acc[mi][ni][2] + b1v[ni][0]) * w2v[ni][0]
                      + gelu_f(acc[mi][ni][3] + b1v[ni][1]) * w2v[ni][1];
        }
    #pragma unroll
    for (int mi = 0; mi < 2; mi++)
        #pragma unroll
        for (int h = 0; h < 2; h++) {
            p[mi][h] += __shfl_xor_sync(0xffffffffu, p[mi][h], 1);
            p[mi][h] += __shfl_xor_sync(0xffffffffu, p[mi][h], 2);
        }
    if (lk == 0) {
        #pragma unroll
        for (int mi = 0; mi < 2; mi++) {
            int r = warpM * 32 + mi * 16 + lr;
            red[r][warpN]     = p[mi][0];
            red[r + 8][warpN] = p[mi][1];
        }
    }
    __syncthreads();
    if (tid < 128) {
        float s = red[tid][0] + red[tid][1] + ab2[0];
        wout[rowBase + tid] = 1.0f / (1.0f + expf(-s));
    }
}

// ---------------------------------------------------------------------------
// Kernel 2: radix-select kth value + band candidate collection + flag reset.
// ---------------------------------------------------------------------------
__global__ __launch_bounds__(256) void select_kernel(const float* __restrict__ w)
{
    __shared__ unsigned sv[NINST];
    __shared__ int hist[8][256];
    __shared__ unsigned s_prefix;
    __shared__ int s_k, s_above, s_cnt;

    const int b = blockIdx.x;
    const int tid = threadIdx.x;
    const int wid = tid >> 5;
    const float* wb = w + b * NINST;

    for (int i = tid; i < NINST; i += 256)
        sv[i] = __float_as_uint(wb[i]);   // weights > 0 -> uint order == float order
    if (tid == 0) { s_prefix = 0u; s_k = TOPK_K; s_above = 0; s_cnt = 0; }
    __syncthreads();

    for (int r = 0; r < 4; r++) {
        #pragma unroll
        for (int h = 0; h < 8; h++) hist[h][tid] = 0;
        __syncthreads();
        const unsigned pref = s_prefix;
        const int sh = 24 - 8 * r;
        for (int i = tid; i < NINST; i += 256) {
            unsigned v = sv[i];
            bool ok = (r == 0) || ((v >> (sh + 8)) == pref);
            if (ok) atomicAdd(&hist[wid][(v >> sh) & 255], 1);
        }
        __syncthreads();
        int s = hist[0][tid];
        #pragma unroll
        for (int h = 1; h < 8; h++) s += hist[h][tid];
        hist[0][tid] = s;
        __syncthreads();
        if (tid == 0) {
            int k = s_k, cum = 0, bsel = 0;
            for (int bb = 255; bb >= 0; --bb) {
                cum += hist[0][bb];
                if (cum >= k) { bsel = bb; s_k = k - (cum - hist[0][bb]); break; }
            }
            s_prefix = (pref << 8) | (unsigned)bsel;
        }
        __syncthreads();
    }

    const float t   = __uint_as_float(s_prefix);
    const float thi = t + BAND;
    const float tlo = t - BAND;

    int la = 0;
    for (int i = tid; i < NINST; i += 256) {
        float wv = __uint_as_float(sv[i]);
        g_flag[b * NINST + i] = 0;
        if (wv > thi) la++;
        else if (wv >= tlo) {
            int p = atomicAdd(&s_cnt, 1);
            if (p < CAP) g_cand[b][p] = i;
        }
    }
    atomicAdd(&s_above, la);
    __syncthreads();
    if (tid == 0) {
        g_thr[b]   = s_prefix;
        g_above[b] = s_above;
        g_ccnt[b]  = s_cnt < CAP ? s_cnt : CAP;
    }
}

// ---------------------------------------------------------------------------
// Kernel 3: exact fp32 score recompute for band candidates.
// grid (CAP, BATCH), block 64; blocks beyond count exit.
// ---------------------------------------------------------------------------
__global__ __launch_bounds__(64) void refine_kernel(
    const float* __restrict__ x,  const float* __restrict__ aW1,
    const float* __restrict__ ab1, const float* __restrict__ aW2,
    const float* __restrict__ ab2)
{
    const int b = blockIdx.y, ci = blockIdx.x;
    if (ci >= g_ccnt[b]) return;
    const int idx = g_cand[b][ci];
    __shared__ float sx[DIM];
    __shared__ float sred[2];
    const int tid = threadIdx.x;
    const float* xr = x + ((long)b * NINST + idx) * DIM;

    for (int d = tid; d < DIM; d += 64) sx[d] = xr[d];
    __syncthreads();

    float acc = 0.f;
    #pragma unroll 8
    for (int d = 0; d < DIM; d++)
        acc += sx[d] * aW1[d * HID + tid];
    float h = gelu_f(acc + ab1[tid]) * aW2[tid];
    #pragma unroll
    for (int off = 16; off >= 1; off >>= 1)
        h += __shfl_down_sync(0xffffffffu, h, off);
    if ((tid & 31) == 0) sred[tid >> 5] = h;
    __syncthreads();
    if (tid == 0) {
        float logit = sred[0] + sred[1] + ab2[0];
        g_cval[b][ci] = 1.0f / (1.0f + expf(-logit));
    }
}

// ---------------------------------------------------------------------------
// Kernel 4: exact ranking among candidates -> flags (value desc, index asc).
// ---------------------------------------------------------------------------
__global__ __launch_bounds__(256) void finalize_kernel()
{
    __shared__ float v[CAP];
    __shared__ int  ix[CAP];
    const int b = blockIdx.x;
    const int tid = threadIdx.x;
    const int cnt  = g_ccnt[b];
    const int need = TOPK_K - g_above[b];

    for (int i = tid; i < cnt; i += 256) { v[i] = g_cval[b][i]; ix[i] = g_cand[b][i]; }
    __syncthreads();
    for (int i = tid; i < cnt; i += 256) {
        float vi = v[i]; int xi = ix[i];
        int rank = 0;
        for (int j = 0; j < cnt; j++)
            rank += (v[j] > vi) || (v[j] == vi && ix[j] < xi);
        if (rank < need) g_flag[b * NINST + xi] = 1;
    }
}

// ---------------------------------------------------------------------------
// Kernel 5: weighted gather-sum, branch-free (threshold OR flag).
// ---------------------------------------------------------------------------
__global__ __launch_bounds__(128) void gather_kernel(
    const float* __restrict__ x, const float* __restrict__ w)
{
    const int b  = blockIdx.y;
    const int rc = blockIdx.x;
    const int r0 = rc * GROWS;
    const int d4 = threadIdx.x * 4;

    const float thi = __uint_as_float(g_thr[b]) + BAND;
    const float* wb = w + b * NINST + r0;
    const unsigned char* fb = g_flag + b * NINST + r0;
    const float* xb = x + ((long)b * NINST + r0) * DIM + d4;

    float4 acc = make_float4(0.f, 0.f, 0.f, 0.f);
    #pragma unroll 8
    for (int i = 0; i < GROWS; i++) {
        float wi = wb[i];
        float ws = (wi > thi || fb[i]) ? wi : 0.0f;
        float4 xv = *reinterpret_cast<const float4*>(xb + (long)i * DIM);
        acc.x += ws * xv.x; acc.y += ws * xv.y;
        acc.z += ws * xv.z; acc.w += ws * xv.w;
    }
    *reinterpret_cast<float4*>(&g_part[(rc * BATCH + b) * DIM + d4]) = acc;
}

// ---------------------------------------------------------------------------
// Kernel 6: emb[b,d] = (sum of partials) / TOPK.
// ---------------------------------------------------------------------------
__global__ __launch_bounds__(512) void emb_kernel()
{
    const int b = blockIdx.x;
    const int d = threadIdx.x;
    float s = 0.f;
    #pragma unroll
    for (int rc = 0; rc < GCHUNKS; rc++)
        s += g_part[(rc * BATCH + b) * DIM + d];
    g_emb[b * DIM + d] = s * (1.0f / (float)TOPK_K);
}

// ---------------------------------------------------------------------------
// Kernels 7/9: split-K GEMM partials for the projection MLP.
// ---------------------------------------------------------------------------
__global__ __launch_bounds__(128) void mlp_part_kernel(
    const float* __restrict__ in, const float* __restrict__ W,
    float* __restrict__ part)
{
    __shared__ float s_in[BATCH][KLEN];
    const int kc = blockIdx.y;
    const int j  = blockIdx.x * 128 + threadIdx.x;

    #pragma unroll
    for (int it = 0; it < (BATCH * KLEN) / 128; it++) {
        int i = it * 128 + threadIdx.x;
        int bb = i / KLEN, dd = i % KLEN;
        s_in[bb][dd] = in[bb * DIM + kc * KLEN + dd];
    }
    __syncthreads();

    float acc[BATCH];
    #pragma unroll
    for (int bb = 0; bb < BATCH; bb++) acc[bb] = 0.f;

    #pragma unroll 4
    for (int dd = 0; dd < KLEN; dd++) {
        float wv = W[(long)(kc * KLEN + dd) * DIM + j];
        #pragma unroll
        for (int bb = 0; bb < BATCH; bb++)
            acc[bb] += s_in[bb][dd] * wv;
    }
    #pragma unroll
    for (int bb = 0; bb < BATCH; bb++)
        part[(kc * BATCH + bb) * DIM + j] = acc[bb];
}

__global__ __launch_bounds__(512) void mlp1_reduce_kernel(const float* __restrict__ bias)
{
    const int b = blockIdx.x;
    const int j = threadIdx.x;
    float s = 0.f;
    #pragma unroll
    for (int kc = 0; kc < KCHUNKS; kc++)
        s += g_p1[(kc * BATCH + b) * DIM + j];
    g_h1[b * DIM + j] = gelu_f(s + bias[j]);
}

__global__ __launch_bounds__(512) void mlp2_reduce_kernel(
    const float* __restrict__ bias, float* __restrict__ out)
{
    const int b = blockIdx.x;
    const int j = threadIdx.x;
    float s = 0.f;
    #pragma unroll
    for (int kc = 0; kc < KCHUNKS; kc++)
        s += g_p2[(kc * BATCH + b) * DIM + j];
    out[b * DIM + j] = s + bias[j];
}

// ---------------------------------------------------------------------------
extern "C" void kernel_launch(void* const* d_in, const int* in_sizes, int n_in,
                              void* d_out, int out_size)
{
    const float* x   = (const float*)d_in[0];
    const float* aW1 = (const float*)d_in[1];
    const float* ab1 = (const float*)d_in[2];
    const float* aW2 = (const float*)d_in[3];
    const float* ab2 = (const float*)d_in[4];
    const float* pW1 = (const float*)d_in[5];
    const float* pb1 = (const float*)d_in[6];
    const float* pW2 = (const float*)d_in[7];
    const float* pb2 = (const float*)d_in[8];

    float* out = (float*)d_out;
    float* proj    = out;                 // [B, DIM]
    float* weights = out + BATCH * DIM;   // [B, NINST]

    float* d_p1;  cudaGetSymbolAddress((void**)&d_p1, g_p1);
    float* d_p2;  cudaGetSymbolAddress((void**)&d_p2, g_p2);
    float* d_emb; cudaGetSymbolAddress((void**)&d_emb, g_emb);
    float* d_h1;  cudaGetSymbolAddress((void**)&d_h1, g_h1);

    conv_w1_kernel<<<(DIM * HID + 255) / 256, 256>>>(aW1);
    attn_kernel<<<(BATCH * NINST) / BM, 256>>>(x, ab1, aW2, ab2, weights);
    select_kernel<<<BATCH, 256>>>(weights);
    refine_kernel<<<dim3(CAP, BATCH), 64>>>(x, aW1, ab1, aW2, ab2);
    finalize_kernel<<<BATCH, 256>>>();
    gather_kernel<<<dim3(GCHUNKS, BATCH), 128>>>(x, weights);
    emb_kernel<<<BATCH, 512>>>();
    mlp_part_kernel<<<dim3(DIM / 128, KCHUNKS), 128>>>(d_emb, pW1, d_p1);
    mlp1_reduce_kernel<<<BATCH, 512>>>(pb1);
    mlp_part_kernel<<<dim3(DIM / 128, KCHUNKS), 128>>>(d_h1, pW2, d_p2);
    mlp2_reduce_kernel<<<BATCH, 512>>>(pb2, proj);
}

// round 7
// speedup vs baseline: 1.5580x; 1.0688x over previous
#include <cuda_runtime.h>
#include <cuda_bf16.h>
#include <math.h>
#include <stdint.h>

#define BATCH 8
#define NINST 8192
#define DIM   512
#define HID   64
#define TOPK_K 2457

#define GCHUNKS 64
#define GROWS   (NINST / GCHUNKS)   // 128

#define KCHUNKS 16
#define KLEN    (DIM / KCHUNKS)     // 32

// attn tiling
#define BM 128
#define BN 64
#define BK 32
#define NCH (DIM / BK)              // 16

#define CAP  512
#define BAND 1e-4f

// scratch (device globals; no allocation allowed)
__device__ __align__(16) __nv_bfloat16 g_w1bh[DIM * HID];  // aW1 hi, [k][n]
__device__ __align__(16) __nv_bfloat16 g_w1bl[DIM * HID];  // aW1 lo, [k][n]
__device__ float    g_part[GCHUNKS * BATCH * DIM];
__device__ float    g_p1[KCHUNKS * BATCH * DIM];
__device__ float    g_p2[KCHUNKS * BATCH * DIM];
__device__ unsigned g_thr[BATCH];                 // approx kth weight (bits)
__device__ int      g_above[BATCH];               // #(w > thr+BAND)
__device__ int      g_ccnt[BATCH];                // candidate count
__device__ int      g_cand[BATCH][CAP];           // candidate indices
__device__ float    g_cval[BATCH][CAP];           // refined fp32 weights
__device__ unsigned char g_flag[BATCH * NINST];   // boundary-selected flags

__device__ __forceinline__ float gelu_f(float v) {
    float u = 0.7978845608028654f * (v + 0.044715f * v * v * v);
    return 0.5f * v * (1.0f + tanhf(u));
}

__device__ __forceinline__ void cp16(uint32_t sdst, const void* gsrc) {
    asm volatile("cp.async.cg.shared.global [%0], [%1], 16;" :: "r"(sdst), "l"(gsrc));
}

__device__ __forceinline__ void hmma(float* c, const unsigned* a, const unsigned* b) {
    asm volatile(
        "mma.sync.aligned.m16n8k16.row.col.f32.bf16.bf16.f32 "
        "{%0,%1,%2,%3}, {%4,%5,%6,%7}, {%8,%9}, {%0,%1,%2,%3};"
        : "+f"(c[0]), "+f"(c[1]), "+f"(c[2]), "+f"(c[3])
        : "r"(a[0]), "r"(a[1]), "r"(a[2]), "r"(a[3]), "r"(b[0]), "r"(b[1]));
}

__device__ __forceinline__ void ldm_x4(unsigned* r, uint32_t addr) {
    asm volatile("ldmatrix.sync.aligned.m8n8.x4.shared.b16 {%0,%1,%2,%3}, [%4];"
                 : "=r"(r[0]), "=r"(r[1]), "=r"(r[2]), "=r"(r[3]) : "r"(addr));
}
__device__ __forceinline__ void ldm_x4t(unsigned* r, uint32_t addr) {
    asm volatile("ldmatrix.sync.aligned.m8n8.x4.trans.shared.b16 {%0,%1,%2,%3}, [%4];"
                 : "=r"(r[0]), "=r"(r[1]), "=r"(r[2]), "=r"(r[3]) : "r"(addr));
}

// ---------------------------------------------------------------------------
// Kernel 0: bf16 hi/lo split of aW1 (layout unchanged, [k][n]).
// ---------------------------------------------------------------------------
__global__ __launch_bounds__(256) void conv_w1_kernel(const float* __restrict__ aW1)
{
    int i = blockIdx.x * 256 + threadIdx.x;
    if (i < DIM * HID) {
        float v = aW1[i];
        __nv_bfloat16 h = __float2bfloat16_rn(v);
        __nv_bfloat16 l = __float2bfloat16_rn(v - __bfloat162float(h));
        g_w1bh[i] = h;
        g_w1bl[i] = l;
    }
}

// ---------------------------------------------------------------------------
// Kernel 1: fused attention-score MLP, bf16 HMMA (3-term hi/lo emulation).
// (unchanged from R6 — validated at rel_err 1.17e-6)
// ---------------------------------------------------------------------------
__global__ __launch_bounds__(256) void attn_kernel(
    const float* __restrict__ x,
    const float* __restrict__ ab1,
    const float* __restrict__ aW2,
    const float* __restrict__ ab2,
    float* __restrict__ wout)
{
    __shared__ __align__(16) __nv_bfloat16 Ah[BM][40];
    __shared__ __align__(16) __nv_bfloat16 Al[BM][40];
    __shared__ __align__(16) __nv_bfloat16 Bh[2][BK][72];
    __shared__ __align__(16) __nv_bfloat16 Bl[2][BK][72];
    __shared__ float red[128][2];

    const int tid   = threadIdx.x;
    const int lane  = tid & 31;
    const int warp  = tid >> 5;
    const int warpM = warp >> 1;
    const int warpN = warp & 1;
    const long rowBase = (long)blockIdx.x * BM;
    const float* xb = x + rowBase * DIM;

    float acc[2][4][4];
    #pragma unroll
    for (int mi = 0; mi < 2; mi++)
        #pragma unroll
        for (int ni = 0; ni < 4; ni++)
            #pragma unroll
            for (int q = 0; q < 4; q++) acc[mi][ni][q] = 0.f;

    auto loadB = [&](int s, int c) {
        int r = tid >> 3, g = tid & 7;
        uint32_t dh = (uint32_t)__cvta_generic_to_shared(&Bh[s][r][g * 8]);
        cp16(dh, g_w1bh + (c * BK + r) * HID + g * 8);
        uint32_t dl = (uint32_t)__cvta_generic_to_shared(&Bl[s][r][g * 8]);
        cp16(dl, g_w1bl + (c * BK + r) * HID + g * 8);
        asm volatile("cp.async.commit_group;");
    };

    const int ar = tid >> 1;
    const int ah = tid & 1;
    const float* xrow = xb + (long)ar * DIM + ah * 16;

    loadB(0, 0);
    float4 xr[4];
    #pragma unroll
    for (int q = 0; q < 4; q++)
        xr[q] = *reinterpret_cast<const float4*>(xrow + q * 4);

    for (int c = 0; c < NCH; c++) {
        unsigned hw[8], lw[8];
        const float* xv = reinterpret_cast<const float*>(xr);
        #pragma unroll
        for (int e = 0; e < 8; e++) {
            float v0 = xv[2 * e], v1 = xv[2 * e + 1];
            __nv_bfloat16 h0 = __float2bfloat16_rn(v0);
            __nv_bfloat16 l0 = __float2bfloat16_rn(v0 - __bfloat162float(h0));
            __nv_bfloat16 h1 = __float2bfloat16_rn(v1);
            __nv_bfloat16 l1 = __float2bfloat16_rn(v1 - __bfloat162float(h1));
            __nv_bfloat162 hp = __halves2bfloat162(h0, h1);
            __nv_bfloat162 lp = __halves2bfloat162(l0, l1);
            hw[e] = *reinterpret_cast<unsigned*>(&hp);
            lw[e] = *reinterpret_cast<unsigned*>(&lp);
        }
        float4 xn[4];
        if (c + 1 < NCH) {
            #pragma unroll
            for (int q = 0; q < 4; q++)
                xn[q] = *reinterpret_cast<const float4*>(xrow + (c + 1) * BK + q * 4);
        }
        __syncthreads();

        {
            char* pa = reinterpret_cast<char*>(&Ah[0][0]) + ar * 80 + ah * 32;
            char* pl = reinterpret_cast<char*>(&Al[0][0]) + ar * 80 + ah * 32;
            *reinterpret_cast<uint4*>(pa)      = make_uint4(hw[0], hw[1], hw[2], hw[3]);
            *reinterpret_cast<uint4*>(pa + 16) = make_uint4(hw[4], hw[5], hw[6], hw[7]);
            *reinterpret_cast<uint4*>(pl)      = make_uint4(lw[0], lw[1], lw[2], lw[3]);
            *reinterpret_cast<uint4*>(pl + 16) = make_uint4(lw[4], lw[5], lw[6], lw[7]);
        }
        if (c + 1 < NCH) {
            loadB((c + 1) & 1, c + 1);
            asm volatile("cp.async.wait_group 1;");
        } else {
            asm volatile("cp.async.wait_group 0;");
        }
        __syncthreads();

        const int st = c & 1;
        #pragma unroll
        for (int ks = 0; ks < 2; ks++) {
            const int k0 = ks * 16;
            unsigned Ahf[2][4], Alf[2][4];
            #pragma unroll
            for (int mi = 0; mi < 2; mi++) {
                int arow2 = warpM * 32 + mi * 16 + (lane & 15);
                int acol  = k0 + ((lane >> 4) << 3);
                uint32_t base = (uint32_t)__cvta_generic_to_shared(&Ah[arow2][acol]);
                ldm_x4(Ahf[mi], base);
                uint32_t basel = (uint32_t)__cvta_generic_to_shared(&Al[arow2][acol]);
                ldm_x4(Alf[mi], basel);
            }
            unsigned Bhf[4][2], Blf[4][2];
            #pragma unroll
            for (int pr = 0; pr < 2; pr++) {
                int brow = k0 + (lane & 15);
                int bcol = warpN * 32 + pr * 16 + ((lane >> 4) << 3);
                unsigned t4[4];
                uint32_t bb = (uint32_t)__cvta_generic_to_shared(&Bh[st][brow][bcol]);
                ldm_x4t(t4, bb);
                Bhf[pr * 2][0] = t4[0]; Bhf[pr * 2][1] = t4[1];
                Bhf[pr * 2 + 1][0] = t4[2]; Bhf[pr * 2 + 1][1] = t4[3];
                uint32_t bl = (uint32_t)__cvta_generic_to_shared(&Bl[st][brow][bcol]);
                ldm_x4t(t4, bl);
                Blf[pr * 2][0] = t4[0]; Blf[pr * 2][1] = t4[1];
                Blf[pr * 2 + 1][0] = t4[2]; Blf[pr * 2 + 1][1] = t4[3];
            }
            #pragma unroll
            for (int mi = 0; mi < 2; mi++)
                #pragma unroll
                for (int ni = 0; ni < 4; ni++) {
                    hmma(acc[mi][ni], Ahf[mi], Bhf[ni]);
                    hmma(acc[mi][ni], Ahf[mi], Blf[ni]);
                    hmma(acc[mi][ni], Alf[mi], Bhf[ni]);
                }
        }
        #pragma unroll
        for (int q = 0; q < 4; q++) xr[q] = xn[q];
    }

    const int lk = lane & 3;
    const int lr = lane >> 2;
    float b1v[4][2], w2v[4][2];
    #pragma unroll
    for (int ni = 0; ni < 4; ni++) {
        int col = warpN * 32 + ni * 8 + 2 * lk;
        b1v[ni][0] = ab1[col];     b1v[ni][1] = ab1[col + 1];
        w2v[ni][0] = aW2[col];     w2v[ni][1] = aW2[col + 1];
    }
    float p[2][2] = {{0.f, 0.f}, {0.f, 0.f}};
    #pragma unroll
    for (int mi = 0; mi < 2; mi++)
        #pragma unroll
        for (int ni = 0; ni < 4; ni++) {
            p[mi][0] += gelu_f(acc[mi][ni][0] + b1v[ni][0]) * w2v[ni][0]
                      + gelu_f(acc[mi][ni][1] + b1v[ni][1]) * w2v[ni][1];
            p[mi][1] += gelu_f(acc[mi][ni][2] + b1v[ni][0]) * w2v[ni][0]
                      + gelu_f(acc[mi][ni][3] + b1v[ni][1]) * w2v[ni][1];
        }
    #pragma unroll
    for (int mi = 0; mi < 2; mi++)
        #pragma unroll
        for (int h = 0; h < 2; h++) {
            p[mi][h] += __shfl_xor_sync(0xffffffffu, p[mi][h], 1);
            p[mi][h] += __shfl_xor_sync(0xffffffffu, p[mi][h], 2);
        }
    if (lk == 0) {
        #pragma unroll
        for (int mi = 0; mi < 2; mi++) {
            int r = warpM * 32 + mi * 16 + lr;
            red[r][warpN]     = p[mi][0];
            red[r + 8][warpN] = p[mi][1];
        }
    }
    __syncthreads();
    if (tid < 128) {
        float s = red[tid][0] + red[tid][1] + ab2[0];
        wout[rowBase + tid] = 1.0f / (1.0f + expf(-s));
    }
}

// ---------------------------------------------------------------------------
// Kernel 2: radix-select kth value + band candidate collection + flag reset.
// ---------------------------------------------------------------------------
__global__ __launch_bounds__(256) void select_kernel(const float* __restrict__ w)
{
    __shared__ unsigned sv[NINST];
    __shared__ int hist[8][256];
    __shared__ unsigned s_prefix;
    __shared__ int s_k, s_above, s_cnt;

    const int b = blockIdx.x;
    const int tid = threadIdx.x;
    const int wid = tid >> 5;
    const float* wb = w + b * NINST;

    for (int i = tid; i < NINST; i += 256)
        sv[i] = __float_as_uint(wb[i]);
    if (tid == 0) { s_prefix = 0u; s_k = TOPK_K; s_above = 0; s_cnt = 0; }
    __syncthreads();

    for (int r = 0; r < 4; r++) {
        #pragma unroll
        for (int h = 0; h < 8; h++) hist[h][tid] = 0;
        __syncthreads();
        const unsigned pref = s_prefix;
        const int sh = 24 - 8 * r;
        for (int i = tid; i < NINST; i += 256) {
            unsigned v = sv[i];
            bool ok = (r == 0) || ((v >> (sh + 8)) == pref);
            if (ok) atomicAdd(&hist[wid][(v >> sh) & 255], 1);
        }
        __syncthreads();
        int s = hist[0][tid];
        #pragma unroll
        for (int h = 1; h < 8; h++) s += hist[h][tid];
        hist[0][tid] = s;
        __syncthreads();
        if (tid == 0) {
            int k = s_k, cum = 0, bsel = 0;
            for (int bb = 255; bb >= 0; --bb) {
                cum += hist[0][bb];
                if (cum >= k) { bsel = bb; s_k = k - (cum - hist[0][bb]); break; }
            }
            s_prefix = (pref << 8) | (unsigned)bsel;
        }
        __syncthreads();
    }

    const float t   = __uint_as_float(s_prefix);
    const float thi = t + BAND;
    const float tlo = t - BAND;

    int la = 0;
    for (int i = tid; i < NINST; i += 256) {
        float wv = __uint_as_float(sv[i]);
        g_flag[b * NINST + i] = 0;
        if (wv > thi) la++;
        else if (wv >= tlo) {
            int p = atomicAdd(&s_cnt, 1);
            if (p < CAP) g_cand[b][p] = i;
        }
    }
    atomicAdd(&s_above, la);
    __syncthreads();
    if (tid == 0) {
        g_thr[b]   = s_prefix;
        g_above[b] = s_above;
        g_ccnt[b]  = s_cnt < CAP ? s_cnt : CAP;
    }
}

// ---------------------------------------------------------------------------
// Kernel 3: exact fp32 score recompute for band candidates.
// grid (32, BATCH), block 256 = 4 K-quarters x 64 hidden per candidate.
// ---------------------------------------------------------------------------
__global__ __launch_bounds__(256) void refine_kernel(
    const float* __restrict__ x,  const float* __restrict__ aW1,
    const float* __restrict__ ab1, const float* __restrict__ aW2,
    const float* __restrict__ ab2)
{
    const int b = blockIdx.y;
    const int cnt = g_ccnt[b];
    __shared__ float sh[4][64];
    __shared__ float sr[2];
    const int tid = threadIdx.x;
    const int q = tid >> 6;       // K quarter
    const int j = tid & 63;       // hidden unit

    for (int ci = blockIdx.x; ci < cnt; ci += 32) {
        const int idx = g_cand[b][ci];
        const float* xr = x + ((long)b * NINST + idx) * DIM + q * 128;
        const float* wp = aW1 + (long)q * 128 * HID + j;

        float a0 = 0.f, a1 = 0.f;
        #pragma unroll 8
        for (int d = 0; d < 128; d += 2) {
            a0 += xr[d]     * wp[(long)d * HID];
            a1 += xr[d + 1] * wp[(long)(d + 1) * HID];
        }
        sh[q][j] = a0 + a1;
        __syncthreads();

        if (tid < 64) {
            float hsum = sh[0][j] + sh[1][j] + sh[2][j] + sh[3][j];
            float hv = gelu_f(hsum + ab1[j]) * aW2[j];
            #pragma unroll
            for (int off = 16; off >= 1; off >>= 1)
                hv += __shfl_down_sync(0xffffffffu, hv, off);
            if ((j & 31) == 0) sr[j >> 5] = hv;
        }
        __syncthreads();
        if (tid == 0) {
            float logit = sr[0] + sr[1] + ab2[0];
            g_cval[b][ci] = 1.0f / (1.0f + expf(-logit));
        }
        __syncthreads();
    }
}

// ---------------------------------------------------------------------------
// Kernel 4: exact ranking among candidates -> flags (value desc, index asc).
// ---------------------------------------------------------------------------
__global__ __launch_bounds__(256) void finalize_kernel()
{
    __shared__ float v[CAP];
    __shared__ int  ix[CAP];
    const int b = blockIdx.x;
    const int tid = threadIdx.x;
    const int cnt  = g_ccnt[b];
    const int need = TOPK_K - g_above[b];

    for (int i = tid; i < cnt; i += 256) { v[i] = g_cval[b][i]; ix[i] = g_cand[b][i]; }
    __syncthreads();
    for (int i = tid; i < cnt; i += 256) {
        float vi = v[i]; int xi = ix[i];
        int rank = 0;
        for (int j = 0; j < cnt; j++)
            rank += (v[j] > vi) || (v[j] == vi && ix[j] < xi);
        if (rank < need) g_flag[b * NINST + xi] = 1;
    }
}

// ---------------------------------------------------------------------------
// Kernel 5: weighted gather-sum, branch-free (threshold OR flag).
// ---------------------------------------------------------------------------
__global__ __launch_bounds__(128) void gather_kernel(
    const float* __restrict__ x, const float* __restrict__ w)
{
    const int b  = blockIdx.y;
    const int rc = blockIdx.x;
    const int r0 = rc * GROWS;
    const int d4 = threadIdx.x * 4;

    const float thi = __uint_as_float(g_thr[b]) + BAND;
    const float* wb = w + b * NINST + r0;
    const unsigned char* fb = g_flag + b * NINST + r0;
    const float* xb = x + ((long)b * NINST + r0) * DIM + d4;

    float4 acc = make_float4(0.f, 0.f, 0.f, 0.f);
    #pragma unroll 8
    for (int i = 0; i < GROWS; i++) {
        float wi = wb[i];
        float ws = (wi > thi || fb[i]) ? wi : 0.0f;
        float4 xv = *reinterpret_cast<const float4*>(xb + (long)i * DIM);
        acc.x += ws * xv.x; acc.y += ws * xv.y;
        acc.z += ws * xv.z; acc.w += ws * xv.w;
    }
    *reinterpret_cast<float4*>(&g_part[(rc * BATCH + b) * DIM + d4]) = acc;
}

// ---------------------------------------------------------------------------
// Kernel 6: mlp1 split-K partials with inline emb reduction.
// part[kc][b][j] = sum_{d in kc} emb[b,d]*pW1[d,j], emb from g_part on the fly.
// ---------------------------------------------------------------------------
__global__ __launch_bounds__(128) void mlp1_part_kernel(
    const float* __restrict__ W, float* __restrict__ part)
{
    __shared__ float s_in[BATCH][KLEN];
    const int kc = blockIdx.y;
    const int j  = blockIdx.x * 128 + threadIdx.x;

    #pragma unroll
    for (int it = 0; it < (BATCH * KLEN) / 128; it++) {
        int i = it * 128 + threadIdx.x;
        int bb = i / KLEN, dd = i % KLEN;
        const float* p = g_part + bb * DIM + kc * KLEN + dd;
        float s0 = 0.f, s1 = 0.f;
        #pragma unroll
        for (int rc = 0; rc < GCHUNKS; rc += 2) {
            s0 += p[(long)rc * BATCH * DIM];
            s1 += p[(long)(rc + 1) * BATCH * DIM];
        }
        s_in[bb][dd] = (s0 + s1) * (1.0f / (float)TOPK_K);
    }
    __syncthreads();

    float acc[BATCH];
    #pragma unroll
    for (int bb = 0; bb < BATCH; bb++) acc[bb] = 0.f;

    #pragma unroll 4
    for (int dd = 0; dd < KLEN; dd++) {
        float wv = W[(long)(kc * KLEN + dd) * DIM + j];
        #pragma unroll
        for (int bb = 0; bb < BATCH; bb++)
            acc[bb] += s_in[bb][dd] * wv;
    }
    #pragma unroll
    for (int bb = 0; bb < BATCH; bb++)
        part[(kc * BATCH + bb) * DIM + j] = acc[bb];
}

// ---------------------------------------------------------------------------
// Kernel 7: mlp2 split-K partials with inline (reduce p1 + bias + gelu).
// ---------------------------------------------------------------------------
__global__ __launch_bounds__(128) void mlp2_part_kernel(
    const float* __restrict__ W, const float* __restrict__ b1,
    float* __restrict__ part)
{
    __shared__ float s_in[BATCH][KLEN];
    const int kc = blockIdx.y;
    const int j  = blockIdx.x * 128 + threadIdx.x;

    #pragma unroll
    for (int it = 0; it < (BATCH * KLEN) / 128; it++) {
        int i = it * 128 + threadIdx.x;
        int bb = i / KLEN, dd = i % KLEN;
        const float* p = g_p1 + bb * DIM + kc * KLEN + dd;
        float s = 0.f;
        #pragma unroll
        for (int c = 0; c < KCHUNKS; c++)
            s += p[(long)c * BATCH * DIM];
        s_in[bb][dd] = gelu_f(s + b1[kc * KLEN + dd]);
    }
    __syncthreads();

    float acc[BATCH];
    #pragma unroll
    for (int bb = 0; bb < BATCH; bb++) acc[bb] = 0.f;

    #pragma unroll 4
    for (int dd = 0; dd < KLEN; dd++) {
        float wv = W[(long)(kc * KLEN + dd) * DIM + j];
        #pragma unroll
        for (int bb = 0; bb < BATCH; bb++)
            acc[bb] += s_in[bb][dd] * wv;
    }
    #pragma unroll
    for (int bb = 0; bb < BATCH; bb++)
        part[(kc * BATCH + bb) * DIM + j] = acc[bb];
}

// ---------------------------------------------------------------------------
// Kernel 8: reduce mlp2 partials + bias -> out.
// ---------------------------------------------------------------------------
__global__ __launch_bounds__(512) void mlp2_reduce_kernel(
    const float* __restrict__ bias, float* __restrict__ out)
{
    const int b = blockIdx.x;
    const int j = threadIdx.x;
    float s = 0.f;
    #pragma unroll
    for (int kc = 0; kc < KCHUNKS; kc++)
        s += g_p2[(kc * BATCH + b) * DIM + j];
    out[b * DIM + j] = s + bias[j];
}

// ---------------------------------------------------------------------------
extern "C" void kernel_launch(void* const* d_in, const int* in_sizes, int n_in,
                              void* d_out, int out_size)
{
    const float* x   = (const float*)d_in[0];
    const float* aW1 = (const float*)d_in[1];
    const float* ab1 = (const float*)d_in[2];
    const float* aW2 = (const float*)d_in[3];
    const float* ab2 = (const float*)d_in[4];
    const float* pW1 = (const float*)d_in[5];
    const float* pb1 = (const float*)d_in[6];
    const float* pW2 = (const float*)d_in[7];
    const float* pb2 = (const float*)d_in[8];

    float* out = (float*)d_out;
    float* proj    = out;                 // [B, DIM]
    float* weights = out + BATCH * DIM;   // [B, NINST]

    float* d_p1;  cudaGetSymbolAddress((void**)&d_p1, g_p1);
    float* d_p2;  cudaGetSymbolAddress((void**)&d_p2, g_p2);

    conv_w1_kernel<<<(DIM * HID + 255) / 256, 256>>>(aW1);
    attn_kernel<<<(BATCH * NINST) / BM, 256>>>(x, ab1, aW2, ab2, weights);
    select_kernel<<<BATCH, 256>>>(weights);
    refine_kernel<<<dim3(32, BATCH), 256>>>(x, aW1, ab1, aW2, ab2);
    finalize_kernel<<<BATCH, 256>>>();
    gather_kernel<<<dim3(GCHUNKS, BATCH), 128>>>(x, weights);
    mlp1_part_kernel<<<dim3(DIM / 128, KCHUNKS), 128>>>(pW1, d_p1);
    mlp2_part_kernel<<<dim3(DIM / 128, KCHUNKS), 128>>>(pW2, pb1, d_p2);
    mlp2_reduce_kernel<<<BATCH, 512>>>(pb2, proj);
}

// round 8
// speedup vs baseline: 1.6589x; 1.0648x over previous
#include <cuda_runtime.h>
#include <cuda_fp16.h>
#include <math.h>
#include <stdint.h>

#define BATCH 8
#define NINST 8192
#define DIM   512
#define HID   64
#define TOPK_K 2457

#define GCHUNKS 64
#define GROWS   (NINST / GCHUNKS)   // 128

#define KCHUNKS 16
#define KLEN    (DIM / KCHUNKS)     // 32

// attn tiling
#define BM 128
#define BN 64
#define BK 32
#define NCH (DIM / BK)              // 16

#define CAP  512
#define BAND 4e-4f

// scratch (device globals; no allocation allowed)
__device__ __align__(16) __half g_w1h[DIM * HID];  // aW1 fp16, [k][n]
__device__ float    g_part[GCHUNKS * BATCH * DIM];
__device__ float    g_p1[KCHUNKS * BATCH * DIM];
__device__ float    g_p2[KCHUNKS * BATCH * DIM];
__device__ unsigned g_thr[BATCH];                 // approx kth weight (bits)
__device__ int      g_above[BATCH];               // #(w > thr+BAND)
__device__ int      g_ccnt[BATCH];                // candidate count
__device__ int      g_cand[BATCH][CAP];           // candidate indices
__device__ float    g_cval[BATCH][CAP];           // refined fp32 weights
__device__ unsigned char g_flag[BATCH * NINST];   // boundary-selected flags

__device__ __forceinline__ float gelu_f(float v) {
    float u = 0.7978845608028654f * (v + 0.044715f * v * v * v);
    return 0.5f * v * (1.0f + tanhf(u));
}

__device__ __forceinline__ void cp16(uint32_t sdst, const void* gsrc) {
    asm volatile("cp.async.cg.shared.global [%0], [%1], 16;" :: "r"(sdst), "l"(gsrc));
}

__device__ __forceinline__ void hmma(float* c, const unsigned* a, const unsigned* b) {
    asm volatile(
        "mma.sync.aligned.m16n8k16.row.col.f32.f16.f16.f32 "
        "{%0,%1,%2,%3}, {%4,%5,%6,%7}, {%8,%9}, {%0,%1,%2,%3};"
        : "+f"(c[0]), "+f"(c[1]), "+f"(c[2]), "+f"(c[3])
        : "r"(a[0]), "r"(a[1]), "r"(a[2]), "r"(a[3]), "r"(b[0]), "r"(b[1]));
}

__device__ __forceinline__ void ldm_x4(unsigned* r, uint32_t addr) {
    asm volatile("ldmatrix.sync.aligned.m8n8.x4.shared.b16 {%0,%1,%2,%3}, [%4];"
                 : "=r"(r[0]), "=r"(r[1]), "=r"(r[2]), "=r"(r[3]) : "r"(addr));
}
__device__ __forceinline__ void ldm_x4t(unsigned* r, uint32_t addr) {
    asm volatile("ldmatrix.sync.aligned.m8n8.x4.trans.shared.b16 {%0,%1,%2,%3}, [%4];"
                 : "=r"(r[0]), "=r"(r[1]), "=r"(r[2]), "=r"(r[3]) : "r"(addr));
}

// ---------------------------------------------------------------------------
// Kernel 0: round aW1 to fp16 (single precision term for B side).
// ---------------------------------------------------------------------------
__global__ __launch_bounds__(256) void conv_w1_kernel(const float* __restrict__ aW1)
{
    int i = blockIdx.x * 256 + threadIdx.x;
    if (i < DIM * HID)
        g_w1h[i] = __float2half_rn(aW1[i]);
}

// ---------------------------------------------------------------------------
// Kernel 1: fused attention-score MLP, fp16 HMMA 2-term (A = hi+lo, B = fp16).
// Block: 128 rows x 64 hid, 256 threads = 8 warps (4M x 2N), warp tile 32x32.
// ---------------------------------------------------------------------------
__global__ __launch_bounds__(256) void attn_kernel(
    const float* __restrict__ x,
    const float* __restrict__ ab1,
    const float* __restrict__ aW2,
    const float* __restrict__ ab2,
    float* __restrict__ wout)
{
    __shared__ __align__(16) __half Ah[BM][40];
    __shared__ __align__(16) __half Al[BM][40];
    __shared__ __align__(16) __half Bh[2][BK][72];
    __shared__ float red[128][2];

    const int tid   = threadIdx.x;
    const int lane  = tid & 31;
    const int warp  = tid >> 5;
    const int warpM = warp >> 1;
    const int warpN = warp & 1;
    const long rowBase = (long)blockIdx.x * BM;
    const float* xb = x + rowBase * DIM;

    float acc[2][4][4];
    #pragma unroll
    for (int mi = 0; mi < 2; mi++)
        #pragma unroll
        for (int ni = 0; ni < 4; ni++)
            #pragma unroll
            for (int q = 0; q < 4; q++) acc[mi][ni][q] = 0.f;

    auto loadB = [&](int s, int c) {
        int r = tid >> 3, g = tid & 7;
        uint32_t dh = (uint32_t)__cvta_generic_to_shared(&Bh[s][r][g * 8]);
        cp16(dh, g_w1h + (c * BK + r) * HID + g * 8);
        asm volatile("cp.async.commit_group;");
    };

    const int ar = tid >> 1;
    const int ah = tid & 1;
    const float* xrow = xb + (long)ar * DIM + ah * 16;

    loadB(0, 0);
    float4 xr[4];
    #pragma unroll
    for (int q = 0; q < 4; q++)
        xr[q] = *reinterpret_cast<const float4*>(xrow + q * 4);

    for (int c = 0; c < NCH; c++) {
        // convert 16 floats -> 8 hi half2 + 8 lo half2
        unsigned hw[8], lw[8];
        const float* xv = reinterpret_cast<const float*>(xr);
        #pragma unroll
        for (int e = 0; e < 8; e++) {
            float v0 = xv[2 * e], v1 = xv[2 * e + 1];
            __half h0 = __float2half_rn(v0);
            __half l0 = __float2half_rn(v0 - __half2float(h0));
            __half h1 = __float2half_rn(v1);
            __half l1 = __float2half_rn(v1 - __half2float(h1));
            __half2 hp = __halves2half2(h0, h1);
            __half2 lp = __halves2half2(l0, l1);
            hw[e] = *reinterpret_cast<unsigned*>(&hp);
            lw[e] = *reinterpret_cast<unsigned*>(&lp);
        }
        float4 xn[4];
        if (c + 1 < NCH) {
            #pragma unroll
            for (int q = 0; q < 4; q++)
                xn[q] = *reinterpret_cast<const float4*>(xrow + (c + 1) * BK + q * 4);
        }
        __syncthreads();   // prior iteration's ldmatrix reads complete

        {
            char* pa = reinterpret_cast<char*>(&Ah[0][0]) + ar * 80 + ah * 32;
            char* pl = reinterpret_cast<char*>(&Al[0][0]) + ar * 80 + ah * 32;
            *reinterpret_cast<uint4*>(pa)      = make_uint4(hw[0], hw[1], hw[2], hw[3]);
            *reinterpret_cast<uint4*>(pa + 16) = make_uint4(hw[4], hw[5], hw[6], hw[7]);
            *reinterpret_cast<uint4*>(pl)      = make_uint4(lw[0], lw[1], lw[2], lw[3]);
            *reinterpret_cast<uint4*>(pl + 16) = make_uint4(lw[4], lw[5], lw[6], lw[7]);
        }
        if (c + 1 < NCH) {
            loadB((c + 1) & 1, c + 1);
            asm volatile("cp.async.wait_group 1;");
        } else {
            asm volatile("cp.async.wait_group 0;");
        }
        __syncthreads();

        const int st = c & 1;
        #pragma unroll
        for (int ks = 0; ks < 2; ks++) {
            const int k0 = ks * 16;
            unsigned Ahf[2][4], Alf[2][4];
            #pragma unroll
            for (int mi = 0; mi < 2; mi++) {
                int arow2 = warpM * 32 + mi * 16 + (lane & 15);
                int acol  = k0 + ((lane >> 4) << 3);
                uint32_t base = (uint32_t)__cvta_generic_to_shared(&Ah[arow2][acol]);
                ldm_x4(Ahf[mi], base);
                uint32_t basel = (uint32_t)__cvta_generic_to_shared(&Al[arow2][acol]);
                ldm_x4(Alf[mi], basel);
            }
            unsigned Bhf[4][2];
            #pragma unroll
            for (int pr = 0; pr < 2; pr++) {
                int brow = k0 + (lane & 15);
                int bcol = warpN * 32 + pr * 16 + ((lane >> 4) << 3);
                unsigned t4[4];
                uint32_t bb = (uint32_t)__cvta_generic_to_shared(&Bh[st][brow][bcol]);
                ldm_x4t(t4, bb);
                Bhf[pr * 2][0] = t4[0]; Bhf[pr * 2][1] = t4[1];
                Bhf[pr * 2 + 1][0] = t4[2]; Bhf[pr * 2 + 1][1] = t4[3];
            }
            #pragma unroll
            for (int mi = 0; mi < 2; mi++)
                #pragma unroll
                for (int ni = 0; ni < 4; ni++) {
                    hmma(acc[mi][ni], Ahf[mi], Bhf[ni]);
                    hmma(acc[mi][ni], Alf[mi], Bhf[ni]);
                }
        }
        #pragma unroll
        for (int q = 0; q < 4; q++) xr[q] = xn[q];
    }

    // epilogue: gelu(acc + b1) . w2, row-reduce, sigmoid
    const int lk = lane & 3;
    const int lr = lane >> 2;
    float b1v[4][2], w2v[4][2];
    #pragma unroll
    for (int ni = 0; ni < 4; ni++) {
        int col = warpN * 32 + ni * 8 + 2 * lk;
        b1v[ni][0] = ab1[col];     b1v[ni][1] = ab1[col + 1];
        w2v[ni][0] = aW2[col];     w2v[ni][1] = aW2[col + 1];
    }
    float p[2][2] = {{0.f, 0.f}, {0.f, 0.f}};
    #pragma unroll
    for (int mi = 0; mi < 2; mi++)
        #pragma unroll
        for (int ni = 0; ni < 4; ni++) {
            p[mi][0] += gelu_f(acc[mi][ni][0] + b1v[ni][0]) * w2v[ni][0]
                      + gelu_f(acc[mi][ni][1] + b1v[ni][1]) * w2v[ni][1];
            p[mi][1] += gelu_f(acc[mi][ni][2] + b1v[ni][0]) * w2v[ni][0]
                      + gelu_f(acc[mi][ni][3] + b1v[ni][1]) * w2v[ni][1];
        }
    #pragma unroll
    for (int mi = 0; mi < 2; mi++)
        #pragma unroll
        for (int h = 0; h < 2; h++) {
            p[mi][h] += __shfl_xor_sync(0xffffffffu, p[mi][h], 1);
            p[mi][h] += __shfl_xor_sync(0xffffffffu, p[mi][h], 2);
        }
    if (lk == 0) {
        #pragma unroll
        for (int mi = 0; mi < 2; mi++) {
            int r = warpM * 32 + mi * 16 + lr;
            red[r][warpN]     = p[mi][0];
            red[r + 8][warpN] = p[mi][1];
        }
    }
    __syncthreads();
    if (tid < 128) {
        float s = red[tid][0] + red[tid][1] + ab2[0];
        wout[rowBase + tid] = 1.0f / (1.0f + expf(-s));
    }
}

// ---------------------------------------------------------------------------
// Kernel 2: radix-select kth value + band candidate collection + flag reset.
// 512 threads per batch block.
// ---------------------------------------------------------------------------
__global__ __launch_bounds__(512) void select_kernel(const float* __restrict__ w)
{
    __shared__ unsigned sv[NINST];
    __shared__ int hist[16][256];
    __shared__ unsigned s_prefix;
    __shared__ int s_k, s_above, s_cnt;

    const int b = blockIdx.x;
    const int tid = threadIdx.x;
    const int wid = tid >> 5;
    const float* wb = w + b * NINST;

    for (int i = tid; i < NINST; i += 512)
        sv[i] = __float_as_uint(wb[i]);
    if (tid == 0) { s_prefix = 0u; s_k = TOPK_K; s_above = 0; s_cnt = 0; }
    __syncthreads();

    for (int r = 0; r < 4; r++) {
        for (int i = tid; i < 16 * 256; i += 512)
            hist[i >> 8][i & 255] = 0;
        __syncthreads();
        const unsigned pref = s_prefix;
        const int sh = 24 - 8 * r;
        for (int i = tid; i < NINST; i += 512) {
            unsigned v = sv[i];
            bool ok = (r == 0) || ((v >> (sh + 8)) == pref);
            if (ok) atomicAdd(&hist[wid][(v >> sh) & 255], 1);
        }
        __syncthreads();
        if (tid < 256) {
            int s = hist[0][tid];
            #pragma unroll
            for (int h = 1; h < 16; h++) s += hist[h][tid];
            hist[0][tid] = s;
        }
        __syncthreads();
        if (tid == 0) {
            int k = s_k, cum = 0, bsel = 0;
            for (int bb = 255; bb >= 0; --bb) {
                cum += hist[0][bb];
                if (cum >= k) { bsel = bb; s_k = k - (cum - hist[0][bb]); break; }
            }
            s_prefix = (pref << 8) | (unsigned)bsel;
        }
        __syncthreads();
    }

    const float t   = __uint_as_float(s_prefix);
    const float thi = t + BAND;
    const float tlo = t - BAND;

    int la = 0;
    for (int i = tid; i < NINST; i += 512) {
        float wv = __uint_as_float(sv[i]);
        g_flag[b * NINST + i] = 0;
        if (wv > thi) la++;
        else if (wv >= tlo) {
            int p = atomicAdd(&s_cnt, 1);
            if (p < CAP) g_cand[b][p] = i;
        }
    }
    atomicAdd(&s_above, la);
    __syncthreads();
    if (tid == 0) {
        g_thr[b]   = s_prefix;
        g_above[b] = s_above;
        g_ccnt[b]  = s_cnt < CAP ? s_cnt : CAP;
    }
}

// ---------------------------------------------------------------------------
// Kernel 3: exact fp32 score recompute for band candidates.
// grid (32, BATCH), block 256; x row staged in smem (coalesced) first.
// ---------------------------------------------------------------------------
__global__ __launch_bounds__(256) void refine_kernel(
    const float* __restrict__ x,  const float* __restrict__ aW1,
    const float* __restrict__ ab1, const float* __restrict__ aW2,
    const float* __restrict__ ab2)
{
    const int b = blockIdx.y;
    const int cnt = g_ccnt[b];
    __shared__ float sx[DIM];
    __shared__ float sh4[4][64];
    __shared__ float sr[2];
    const int tid = threadIdx.x;
    const int q = tid >> 6;       // K quarter
    const int j = tid & 63;       // hidden unit

    for (int ci = blockIdx.x; ci < cnt; ci += 32) {
        const int idx = g_cand[b][ci];
        const float* xr = x + ((long)b * NINST + idx) * DIM;
        sx[tid]       = xr[tid];
        sx[tid + 256] = xr[tid + 256];
        __syncthreads();

        const float* wp = aW1 + (long)q * 128 * HID + j;
        const float* xq = sx + q * 128;
        float a0 = 0.f, a1 = 0.f;
        #pragma unroll
        for (int d = 0; d < 128; d += 2) {
            a0 += xq[d]     * wp[(long)d * HID];
            a1 += xq[d + 1] * wp[(long)(d + 1) * HID];
        }
        sh4[q][j] = a0 + a1;
        __syncthreads();

        if (tid < 64) {
            float hsum = sh4[0][j] + sh4[1][j] + sh4[2][j] + sh4[3][j];
            float hv = gelu_f(hsum + ab1[j]) * aW2[j];
            #pragma unroll
            for (int off = 16; off >= 1; off >>= 1)
                hv += __shfl_down_sync(0xffffffffu, hv, off);
            if ((j & 31) == 0) sr[j >> 5] = hv;
        }
        __syncthreads();
        if (tid == 0) {
            float logit = sr[0] + sr[1] + ab2[0];
            g_cval[b][ci] = 1.0f / (1.0f + expf(-logit));
        }
        __syncthreads();
    }
}

// ---------------------------------------------------------------------------
// Kernel 4: exact ranking among candidates -> flags (value desc, index asc).
// ---------------------------------------------------------------------------
__global__ __launch_bounds__(256) void finalize_kernel()
{
    __shared__ float v[CAP];
    __shared__ int  ix[CAP];
    const int b = blockIdx.x;
    const int tid = threadIdx.x;
    const int cnt  = g_ccnt[b];
    const int need = TOPK_K - g_above[b];

    for (int i = tid; i < cnt; i += 256) { v[i] = g_cval[b][i]; ix[i] = g_cand[b][i]; }
    __syncthreads();
    for (int i = tid; i < cnt; i += 256) {
        float vi = v[i]; int xi = ix[i];
        int rank = 0;
        for (int j = 0; j < cnt; j++)
            rank += (v[j] > vi) || (v[j] == vi && ix[j] < xi);
        if (rank < need) g_flag[b * NINST + xi] = 1;
    }
}

// ---------------------------------------------------------------------------
// Kernel 5: weighted gather-sum, branch-free (threshold OR flag).
// ---------------------------------------------------------------------------
__global__ __launch_bounds__(128) void gather_kernel(
    const float* __restrict__ x, const float* __restrict__ w)
{
    const int b  = blockIdx.y;
    const int rc = blockIdx.x;
    const int r0 = rc * GROWS;
    const int d4 = threadIdx.x * 4;

    const float thi = __uint_as_float(g_thr[b]) + BAND;
    const float* wb = w + b * NINST + r0;
    const unsigned char* fb = g_flag + b * NINST + r0;
    const float* xb = x + ((long)b * NINST + r0) * DIM + d4;

    float4 acc = make_float4(0.f, 0.f, 0.f, 0.f);
    #pragma unroll 8
    for (int i = 0; i < GROWS; i++) {
        float wi = wb[i];
        float ws = (wi > thi || fb[i]) ? wi : 0.0f;
        float4 xv = *reinterpret_cast<const float4*>(xb + (long)i * DIM);
        acc.x += ws * xv.x; acc.y += ws * xv.y;
        acc.z += ws * xv.z; acc.w += ws * xv.w;
    }
    *reinterpret_cast<float4*>(&g_part[(rc * BATCH + b) * DIM + d4]) = acc;
}

// ---------------------------------------------------------------------------
// Kernel 6: mlp1 split-K partials with inline emb reduction.
// ---------------------------------------------------------------------------
__global__ __launch_bounds__(128) void mlp1_part_kernel(
    const float* __restrict__ W, float* __restrict__ part)
{
    __shared__ float s_in[BATCH][KLEN];
    const int kc = blockIdx.y;
    const int j  = blockIdx.x * 128 + threadIdx.x;

    #pragma unroll
    for (int it = 0; it < (BATCH * KLEN) / 128; it++) {
        int i = it * 128 + threadIdx.x;
        int bb = i / KLEN, dd = i % KLEN;
        const float* p = g_part + bb * DIM + kc * KLEN + dd;
        float s0 = 0.f, s1 = 0.f;
        #pragma unroll
        for (int rc = 0; rc < GCHUNKS; rc += 2) {
            s0 += p[(long)rc * BATCH * DIM];
            s1 += p[(long)(rc + 1) * BATCH * DIM];
        }
        s_in[bb][dd] = (s0 + s1) * (1.0f / (float)TOPK_K);
    }
    __syncthreads();

    float acc[BATCH];
    #pragma unroll
    for (int bb = 0; bb < BATCH; bb++) acc[bb] = 0.f;

    #pragma unroll 4
    for (int dd = 0; dd < KLEN; dd++) {
        float wv = W[(long)(kc * KLEN + dd) * DIM + j];
        #pragma unroll
        for (int bb = 0; bb < BATCH; bb++)
            acc[bb] += s_in[bb][dd] * wv;
    }
    #pragma unroll
    for (int bb = 0; bb < BATCH; bb++)
        part[(kc * BATCH + bb) * DIM + j] = acc[bb];
}

// ---------------------------------------------------------------------------
// Kernel 7: mlp2 split-K partials with inline (reduce p1 + bias + gelu).
// ---------------------------------------------------------------------------
__global__ __launch_bounds__(128) void mlp2_part_kernel(
    const float* __restrict__ W, const float* __restrict__ b1,
    float* __restrict__ part)
{
    __shared__ float s_in[BATCH][KLEN];
    const int kc = blockIdx.y;
    const int j  = blockIdx.x * 128 + threadIdx.x;

    #pragma unroll
    for (int it = 0; it < (BATCH * KLEN) / 128; it++) {
        int i = it * 128 + threadIdx.x;
        int bb = i / KLEN, dd = i % KLEN;
        const float* p = g_p1 + bb * DIM + kc * KLEN + dd;
        float s = 0.f;
        #pragma unroll
        for (int c = 0; c < KCHUNKS; c++)
            s += p[(long)c * BATCH * DIM];
        s_in[bb][dd] = gelu_f(s + b1[kc * KLEN + dd]);
    }
    __syncthreads();

    float acc[BATCH];
    #pragma unroll
    for (int bb = 0; bb < BATCH; bb++) acc[bb] = 0.f;

    #pragma unroll 4
    for (int dd = 0; dd < KLEN; dd++) {
        float wv = W[(long)(kc * KLEN + dd) * DIM + j];
        #pragma unroll
        for (int bb = 0; bb < BATCH; bb++)
            acc[bb] += s_in[bb][dd] * wv;
    }
    #pragma unroll
    for (int bb = 0; bb < BATCH; bb++)
        part[(kc * BATCH + bb) * DIM + j] = acc[bb];
}

// ---------------------------------------------------------------------------
// Kernel 8: reduce mlp2 partials + bias -> out.
// ---------------------------------------------------------------------------
__global__ __launch_bounds__(512) void mlp2_reduce_kernel(
    const float* __restrict__ bias, float* __restrict__ out)
{
    const int b = blockIdx.x;
    const int j = threadIdx.x;
    float s = 0.f;
    #pragma unroll
    for (int kc = 0; kc < KCHUNKS; kc++)
        s += g_p2[(kc * BATCH + b) * DIM + j];
    out[b * DIM + j] = s + bias[j];
}

// ---------------------------------------------------------------------------
extern "C" void kernel_launch(void* const* d_in, const int* in_sizes, int n_in,
                              void* d_out, int out_size)
{
    const float* x   = (const float*)d_in[0];
    const float* aW1 = (const float*)d_in[1];
    const float* ab1 = (const float*)d_in[2];
    const float* aW2 = (const float*)d_in[3];
    const float* ab2 = (const float*)d_in[4];
    const float* pW1 = (const float*)d_in[5];
    const float* pb1 = (const float*)d_in[6];
    const float* pW2 = (const float*)d_in[7];
    const float* pb2 = (const float*)d_in[8];

    float* out = (float*)d_out;
    float* proj    = out;                 // [B, DIM]
    float* weights = out + BATCH * DIM;   // [B, NINST]

    float* d_p1;  cudaGetSymbolAddress((void**)&d_p1, g_p1);
    float* d_p2;  cudaGetSymbolAddress((void**)&d_p2, g_p2);

    conv_w1_kernel<<<(DIM * HID + 255) / 256, 256>>>(aW1);
    attn_kernel<<<(BATCH * NINST) / BM, 256>>>(x, ab1, aW2, ab2, weights);
    select_kernel<<<BATCH, 512>>>(weights);
    refine_kernel<<<dim3(32, BATCH), 256>>>(x, aW1, ab1, aW2, ab2);
    finalize_kernel<<<BATCH, 256>>>();
    gather_kernel<<<dim3(GCHUNKS, BATCH), 128>>>(x, weights);
    mlp1_part_kernel<<<dim3(DIM / 128, KCHUNKS), 128>>>(pW1, d_p1);
    mlp2_part_kernel<<<dim3(DIM / 128, KCHUNKS), 128>>>(pW2, pb1, d_p2);
    mlp2_reduce_kernel<<<BATCH, 512>>>(pb2, proj);
}